// round 7
// baseline (speedup 1.0000x reference)
#include <cuda_runtime.h>
#include <cstddef>

// Problem constants (fixed by the dataset)
#define BATCH   64
#define NNODE   16384              // nodes per sample
#define BNODES  1048576            // BATCH * NNODE
#define EDGES   8388608
#define COUT    8
#define DIM     128
#define BOUT    16

// fc1 GEMM tiling
#define NB_FC1        1024         // blocks for fc1
#define NODES_PER_BLK 16           // nodes per fc1 block (=> 128 K-rows)

// -------- device scratch (no allocations allowed) --------
__device__ float g_deg[BNODES];
__device__ float g_dinv[BNODES];
__device__ float g_u[BNODES];                      // dinv * x
__device__ float g_S[BNODES];                      // scatter accumulator
__device__ float g_part[(size_t)NB_FC1 * BATCH * DIM];   // 32 MB fc1 partials
__device__ float g_h1[BATCH * DIM];                // after fc1 + lrelu

// -------- f32x2 packed-FMA helpers (FFMA2 only reachable via PTX) --------
__device__ __forceinline__ unsigned long long pk2(float lo, float hi) {
    unsigned long long r;
    asm("mov.b64 %0, {%1,%2};" : "=l"(r) : "f"(lo), "f"(hi));
    return r;
}
__device__ __forceinline__ unsigned long long dup2(float v) { return pk2(v, v); }
__device__ __forceinline__ void fma2(unsigned long long& d, unsigned long long a,
                                     unsigned long long b) {
    asm("fma.rn.f32x2 %0, %1, %2, %0;" : "+l"(d) : "l"(a), "l"(b));
}
__device__ __forceinline__ void unpk2(unsigned long long v, float& lo, float& hi) {
    asm("mov.b64 {%0,%1}, %2;" : "=f"(lo), "=f"(hi) : "l"(v));
}

__device__ __forceinline__ float lrelu(float v) { return v > 0.f ? v : 0.01f * v; }

// -------- kernels --------

// zero g_deg only (g_S is zeroed later inside k_dinv, before k_scatter uses it)
__global__ void k_init() {
    int i = blockIdx.x * blockDim.x + threadIdx.x;   // < BNODES/4
    ((float4*)g_deg)[i] = make_float4(0.f, 0.f, 0.f, 0.f);
}

// deg[row] += edge_attr  (4 edges / thread)
__global__ void k_deg(const int* __restrict__ row, const float* __restrict__ ea) {
    int i = blockIdx.x * blockDim.x + threadIdx.x;   // < EDGES/4
    int4   r = ((const int4*)row)[i];
    float4 e = ((const float4*)ea)[i];
    atomicAdd(&g_deg[r.x], e.x);
    atomicAdd(&g_deg[r.y], e.y);
    atomicAdd(&g_deg[r.z], e.z);
    atomicAdd(&g_deg[r.w], e.w);
}

// dinv = deg>0 ? rsqrt(deg) : 0 ;  u = dinv * x ;  also zero g_S for k_scatter
__global__ void k_dinv(const float* __restrict__ x) {
    int i = blockIdx.x * blockDim.x + threadIdx.x;   // < BNODES
    float d  = g_deg[i];
    float dv = d > 0.f ? rsqrtf(d) : 0.f;
    g_dinv[i] = dv;
    g_u[i]    = dv * x[i];
    g_S[i]    = 0.f;
}

// S[row] += ea * u[col]   (Tx1 = -dinv * S applied later)
__global__ void k_scatter(const int* __restrict__ row, const int* __restrict__ col,
                          const float* __restrict__ ea) {
    int i = blockIdx.x * blockDim.x + threadIdx.x;   // < EDGES/4
    int4   r = ((const int4*)row)[i];
    int4   c = ((const int4*)col)[i];
    float4 e = ((const float4*)ea)[i];
    atomicAdd(&g_S[r.x], e.x * g_u[c.x]);
    atomicAdd(&g_S[r.y], e.y * g_u[c.y]);
    atomicAdd(&g_S[r.z], e.z * g_u[c.z]);
    atomicAdd(&g_S[r.w], e.w * g_u[c.w]);
}

// fc1 GEMM:  out1[64][128] += h[64, k-slice] @ fc1_W[k-slice, 128]
// h is built on the fly from x, dinv, S (never materialized to DRAM).
// Block = 16 nodes (128 K rows). Thread grid 8(bg) x 32(dg); tile 8b x 4d,
// accumulated as f32x2 pairs (packed FFMA2 = full-rate fp32).
__global__ __launch_bounds__(256) void k_fc1(
    const float* __restrict__ x,
    const float* __restrict__ W0, const float* __restrict__ W1,
    const float* __restrict__ cb, const float* __restrict__ fc1W) {

    __shared__ float h_s[128 * 64];   // [k-row][batch]  32 KB
    int tid = threadIdx.x;
    int n0  = blockIdx.x * NODES_PER_BLK;

    float w0[COUT], w1[COUT], b8[COUT];
#pragma unroll
    for (int c = 0; c < COUT; c++) { w0[c] = W0[c]; w1[c] = W1[c]; b8[c] = cb[c]; }

    // Build h tile: 1024 (b,node) pairs, 4 per thread, 8 channels each.
#pragma unroll
    for (int p = 0; p < 4; p++) {
        int pi = p * 256 + tid;
        int b  = pi & 63;
        int nl = pi >> 6;                 // 0..15
        int g  = b * NNODE + n0 + nl;
        float xv = x[g];
        float tv = -g_dinv[g] * g_S[g];   // Tx1
#pragma unroll
        for (int c = 0; c < COUT; c++) {
            float hv = fmaf(xv, w0[c], fmaf(tv, w1[c], b8[c]));
            h_s[(nl * COUT + c) * 64 + b] = lrelu(hv);
        }
    }
    __syncthreads();

    int dg = tid & 31;   // d group: cols dg*4 .. dg*4+3
    int bg = tid >> 5;   // b group: rows bg*8 .. bg*8+7

    unsigned long long acc[4][4];
#pragma unroll
    for (int p = 0; p < 4; p++)
#pragma unroll
        for (int j = 0; j < 4; j++) acc[p][j] = 0ull;   // {0.f,0.f}

    const float4* Wp = (const float4*)fc1W + (size_t)n0 * COUT * (DIM / 4) + dg;

#pragma unroll 4
    for (int k = 0; k < NODES_PER_BLK * COUT; k++) {
        float4 w4 = __ldg(Wp + (size_t)k * (DIM / 4));
        float4 hA = *(const float4*)&h_s[k * 64 + bg * 8];
        float4 hB = *(const float4*)&h_s[k * 64 + bg * 8 + 4];

        unsigned long long hp0 = pk2(hA.x, hA.y);
        unsigned long long hp1 = pk2(hA.z, hA.w);
        unsigned long long hp2 = pk2(hB.x, hB.y);
        unsigned long long hp3 = pk2(hB.z, hB.w);
        unsigned long long wd0 = dup2(w4.x), wd1 = dup2(w4.y);
        unsigned long long wd2 = dup2(w4.z), wd3 = dup2(w4.w);

        fma2(acc[0][0], hp0, wd0); fma2(acc[0][1], hp0, wd1);
        fma2(acc[0][2], hp0, wd2); fma2(acc[0][3], hp0, wd3);
        fma2(acc[1][0], hp1, wd0); fma2(acc[1][1], hp1, wd1);
        fma2(acc[1][2], hp1, wd2); fma2(acc[1][3], hp1, wd3);
        fma2(acc[2][0], hp2, wd0); fma2(acc[2][1], hp2, wd1);
        fma2(acc[2][2], hp2, wd2); fma2(acc[2][3], hp2, wd3);
        fma2(acc[3][0], hp3, wd0); fma2(acc[3][1], hp3, wd1);
        fma2(acc[3][2], hp3, wd2); fma2(acc[3][3], hp3, wd3);
    }

    float* outp = g_part + (size_t)blockIdx.x * (BATCH * DIM);
#pragma unroll
    for (int p = 0; p < 4; p++) {
        float lo[4], hi[4];
#pragma unroll
        for (int j = 0; j < 4; j++) unpk2(acc[p][j], lo[j], hi[j]);
        int b0 = bg * 8 + p * 2;
        *(float4*)&outp[(b0 + 0) * DIM + dg * 4] = make_float4(lo[0], lo[1], lo[2], lo[3]);
        *(float4*)&outp[(b0 + 1) * DIM + dg * 4] = make_float4(hi[0], hi[1], hi[2], hi[3]);
    }
}

// reduce fc1 partials, add bias, lrelu  (8192 outputs)
// v2: two-level reduction. 256 blocks x 256 threads. Each warp owns 32
// consecutive j (coalesced 128B lines); each thread sums a 128-partial slice;
// smem reduce across the 8 slices, then bias + lrelu.
__global__ __launch_bounds__(256) void k_reduce(const float* __restrict__ fc1b) {
    __shared__ float red[8][32];
    int tid   = threadIdx.x;
    int slice = tid >> 5;                 // 0..7
    int jl    = tid & 31;
    int j     = blockIdx.x * 32 + jl;     // < 8192

    const float* p = g_part + (size_t)(slice * (NB_FC1 / 8)) * (BATCH * DIM) + j;
    float s0 = 0.f, s1 = 0.f, s2 = 0.f, s3 = 0.f;
#pragma unroll 4
    for (int k = 0; k < NB_FC1 / 8; k += 4) {
        s0 += p[(size_t)(k + 0) * (BATCH * DIM)];
        s1 += p[(size_t)(k + 1) * (BATCH * DIM)];
        s2 += p[(size_t)(k + 2) * (BATCH * DIM)];
        s3 += p[(size_t)(k + 3) * (BATCH * DIM)];
    }
    red[slice][jl] = (s0 + s1) + (s2 + s3);
    __syncthreads();

    if (slice == 0) {
        float s = 0.f;
#pragma unroll
        for (int q = 0; q < 8; q++) s += red[q][jl];
        s += fc1b[j & (DIM - 1)];
        g_h1[j] = lrelu(s);
    }
}

// fc2 + lrelu + fc3  (one block per batch row)
__global__ __launch_bounds__(DIM) void k_head(
    const float* __restrict__ fc2W, const float* __restrict__ fc2b,
    const float* __restrict__ fc3W, const float* __restrict__ fc3b,
    float* __restrict__ out) {
    __shared__ float h1s[DIM];
    __shared__ float h2s[DIM];
    int b = blockIdx.x, d = threadIdx.x;
    h1s[d] = g_h1[b * DIM + d];
    __syncthreads();
    float a = fc2b[d];
#pragma unroll 16
    for (int k = 0; k < DIM; k++) a = fmaf(h1s[k], fc2W[k * DIM + d], a);
    h2s[d] = lrelu(a);
    __syncthreads();
    if (d < BOUT) {
        float o = fc3b[d];
#pragma unroll 16
        for (int k = 0; k < DIM; k++) o = fmaf(h2s[k], fc3W[k * BOUT + d], o);
        out[b * BOUT + d] = o;
    }
}

// -------- launch --------
extern "C" void kernel_launch(void* const* d_in, const int* in_sizes, int n_in,
                              void* d_out, int out_size) {
    const float* x    = (const float*)d_in[0];
    const int*   ei   = (const int*)d_in[1];     // [2][EDGES] int32
    const float* ea   = (const float*)d_in[2];
    const float* W0   = (const float*)d_in[3];
    const float* W1   = (const float*)d_in[4];
    const float* cb   = (const float*)d_in[5];
    const float* fc1W = (const float*)d_in[6];
    const float* fc1b = (const float*)d_in[7];
    const float* fc2W = (const float*)d_in[8];
    const float* fc2b = (const float*)d_in[9];
    const float* fc3W = (const float*)d_in[10];
    const float* fc3b = (const float*)d_in[11];
    float* out = (float*)d_out;

    const int* row = ei;
    const int* col = ei + EDGES;

    k_init<<<BNODES / 4 / 256, 256>>>();
    k_deg<<<EDGES / 4 / 256, 256>>>(row, ea);
    k_dinv<<<BNODES / 256, 256>>>(x);
    k_scatter<<<EDGES / 4 / 256, 256>>>(row, col, ea);
    k_fc1<<<NB_FC1, 256>>>(x, W0, W1, cb, fc1W);
    k_reduce<<<(BATCH * DIM) / 32, 256>>>(fc1b);
    k_head<<<BATCH, DIM>>>(fc2W, fc2b, fc3W, fc3b, out);
}